// round 13
// baseline (speedup 1.0000x reference)
#include <cuda_runtime.h>
#include <math.h>

#define B 16
#define T 2048
#define D 768
#define D4 192          // D/4 float4 lanes
#define A 5
#define NSEG1 32        // t-segments for mean partials (64 t each)
#define NSEG 32         // t-segments for agent_v partials (64 t each)
#define TSEG 64
#define NSKT 256        // skt blocks per b (8 t each)

typedef unsigned long long ull;

// ---- packed f32x2 helpers (Blackwell; bit-identical rounding to FFMA) ----
__device__ __forceinline__ ull pack2(float x) {
    ull r; asm("mov.b64 %0, {%1, %1};" : "=l"(r) : "f"(x)); return r;
}
__device__ __forceinline__ ull fma2(ull a, ull b, ull c) {
    ull d; asm("fma.rn.f32x2 %0, %1, %2, %3;" : "=l"(d) : "l"(a), "l"(b), "l"(c));
    return d;
}
__device__ __forceinline__ ull mul2(ull a, ull b) {
    ull d; asm("mul.rn.f32x2 %0, %1, %2;" : "=l"(d) : "l"(a), "l"(b));
    return d;
}

// ---- scratch (device globals; no allocation) ----
__device__ float4 g_mpart[B][NSEG1][D4];       // 1.5 MB (L2-hot)
__device__ float4 g_m[B][D4];                  // 48 KB
__device__ float  g_w[B][A][T];                // 640 KB unnormalized weights
__device__ float  g_wsp[B][A][NSKT];           // per-block weight sums
__device__ float4 g_avpart[B][NSEG][A][D4];    // 7.9 MB (L2-hot, unnormalized)
__device__ float4 g_av[B][A][D4];              // 240 KB

// ---------------------------------------------------------------
// Kernel 1: masked-sum partials of q. grid (NSEG1, B) = 512, block 192.
// Batches of 8 keep 8 LDG.128 in flight; mask==0 rows predicated off.
__global__ void __launch_bounds__(192, 4)
k_mean_part(const float4* __restrict__ q, const int* __restrict__ mask) {
    cudaTriggerProgrammaticLaunchCompletion();
    const int seg = blockIdx.x, b = blockIdx.y;
    const int tid = threadIdx.x;               // d4 lane
    const int t0 = seg * (T / NSEG1);
    __shared__ int smask[T / NSEG1];
    if (tid < T / NSEG1) smask[tid] = mask[b * T + t0 + tid];
    __syncthreads();
    const float4* qb = q + ((size_t)b * T + t0) * D4 + tid;
    float4 acc = make_float4(0.f, 0.f, 0.f, 0.f);
    for (int tt = 0; tt < T / NSEG1; tt += 8) {
        float4 vv[8];
        #pragma unroll
        for (int j = 0; j < 8; ++j) {
            if (smask[tt + j]) vv[j] = qb[(size_t)(tt + j) * D4];
            else               vv[j] = make_float4(0.f, 0.f, 0.f, 0.f);
        }
        #pragma unroll
        for (int j = 0; j < 8; ++j) {
            acc.x += vv[j].x; acc.y += vv[j].y;
            acc.z += vv[j].z; acc.w += vv[j].w;
        }
    }
    g_mpart[b][seg][tid] = acc;
}

// Kernel 1b: finish mean (divide by T, torch semantics). B*D4 threads.
__global__ void k_mean_fin() {
    cudaGridDependencySynchronize();
    cudaTriggerProgrammaticLaunchCompletion();
    int i = blockIdx.x * 256 + threadIdx.x;
    if (i >= B * D4) return;
    int b = i / D4, d = i % D4;
    float4 acc = make_float4(0.f, 0.f, 0.f, 0.f);
    #pragma unroll
    for (int s = 0; s < NSEG1; ++s) {
        float4 v = g_mpart[b][s][d];
        acc.x += v.x; acc.y += v.y; acc.z += v.z; acc.w += v.w;
    }
    const float inv = 1.0f / (float)T;
    acc.x *= inv; acc.y *= inv; acc.z *= inv; acc.w *= inv;
    g_m[b][d] = acc;
}

// ---------------------------------------------------------------
// Kernel 2: s[b,t] = k[b,t,:].m[b,:]; emit UNNORMALIZED weights
// e[a,t] = exp(s_t + b1[a,t]) and per-block weight sums.
// PDL: k rows prefetched into registers BEFORE syncing on g_m.
// grid (NSKT, B), block 256 (8 warps, one t each).
__global__ void k_skt(const float4* __restrict__ k,
                      const float* __restrict__ b1) {
    const int b = blockIdx.y;
    const int warp = threadIdx.x >> 5;
    const int lane = threadIdx.x & 31;
    const int t0 = blockIdx.x * 8;
    const int t = t0 + warp;
    const float4* kr = k + ((size_t)b * T + t) * D4;
    float4 kv[D4 / 32];                        // 6 x LDG.128 prologue
    #pragma unroll
    for (int i = 0; i < D4 / 32; ++i) kv[i] = kr[lane + i * 32];

    cudaGridDependencySynchronize();           // g_m ready
    cudaTriggerProgrammaticLaunchCompletion();

    __shared__ float4 sm[D4];
    __shared__ float ss[8];
    __shared__ float se[8][8];                 // [t][a] padded
    if (threadIdx.x < D4) sm[threadIdx.x] = g_m[b][threadIdx.x];
    __syncthreads();
    float acc = 0.f;
    #pragma unroll
    for (int i = 0; i < D4 / 32; ++i) {
        float4 mv = sm[lane + i * 32];
        acc += kv[i].x * mv.x + kv[i].y * mv.y + kv[i].z * mv.z + kv[i].w * mv.w;
    }
    #pragma unroll
    for (int o = 16; o; o >>= 1) acc += __shfl_down_sync(0xffffffffu, acc, o);
    if (lane == 0) ss[warp] = acc;
    __syncthreads();
    if (threadIdx.x < A * 8) {
        const int a = threadIdx.x >> 3, j = threadIdx.x & 7;
        float e = expf(ss[j] + b1[a * T + t0 + j]);
        g_w[b][a][t0 + j] = e;
        se[j][a] = e;
    }
    __syncthreads();
    if (threadIdx.x < A) {
        const int a = threadIdx.x;
        float sum = 0.f;
        #pragma unroll
        for (int j = 0; j < 8; ++j) sum += se[j][a];
        g_wsp[b][a][blockIdx.x] = sum;
    }
}

// ---------------------------------------------------------------
// Kernel 3: agent_v partials — packed f32x2 accumulation.
// PDL: batch 0 of v prefetched before syncing on g_w.
// grid (NSEG, B) = 512 blocks, block 192. Reads v once (100MB), MLP 8.
__global__ void __launch_bounds__(192, 4)
k_av_part(const ulonglong2* __restrict__ v) {
    const int seg = blockIdx.x, b = blockIdx.y;
    const int tid = threadIdx.x;
    const int t0 = seg * TSEG;
    const ulonglong2* vb = v + ((size_t)b * T + t0) * D4 + tid;

    ulonglong2 vv[8];                           // prologue: batch 0
    #pragma unroll
    for (int j = 0; j < 8; ++j) vv[j] = vb[(size_t)j * D4];

    cudaGridDependencySynchronize();            // g_w ready
    cudaTriggerProgrammaticLaunchCompletion();

    __shared__ ull sw2[TSEG][8];                // (w,w) packed per [t][a]
    for (int i = tid; i < TSEG * A; i += 192) {
        int a = i / TSEG, tt = i % TSEG;        // coalesced g_w reads
        sw2[tt][a] = pack2(g_w[b][a][t0 + tt]);
    }
    __syncthreads();

    ull aL0 = 0, aL1 = 0, aL2 = 0, aL3 = 0, aL4 = 0;
    ull aH0 = 0, aH1 = 0, aH2 = 0, aH3 = 0, aH4 = 0;
    for (int tt = 0; tt < TSEG; tt += 8) {
        if (tt) {
            #pragma unroll
            for (int j = 0; j < 8; ++j) vv[j] = vb[(size_t)(tt + j) * D4];
        }
        #pragma unroll
        for (int j = 0; j < 8; ++j) {
            const int r = tt + j;
            ull w0 = sw2[r][0], w1 = sw2[r][1], w2 = sw2[r][2],
                w3 = sw2[r][3], w4 = sw2[r][4];
            aL0 = fma2(w0, vv[j].x, aL0); aH0 = fma2(w0, vv[j].y, aH0);
            aL1 = fma2(w1, vv[j].x, aL1); aH1 = fma2(w1, vv[j].y, aH1);
            aL2 = fma2(w2, vv[j].x, aL2); aH2 = fma2(w2, vv[j].y, aH2);
            aL3 = fma2(w3, vv[j].x, aL3); aH3 = fma2(w3, vv[j].y, aH3);
            aL4 = fma2(w4, vv[j].x, aL4); aH4 = fma2(w4, vv[j].y, aH4);
        }
    }
    ulonglong2* gp = (ulonglong2*)&g_avpart[b][seg][0][tid];
    gp[0 * D4] = make_ulonglong2(aL0, aH0);
    gp[1 * D4] = make_ulonglong2(aL1, aH1);
    gp[2 * D4] = make_ulonglong2(aL2, aH2);
    gp[3 * D4] = make_ulonglong2(aL3, aH3);
    gp[4 * D4] = make_ulonglong2(aL4, aH4);
}

// ---------------------------------------------------------------
// Kernel 3b: reduce agent_v partials (L2-hot) + normalize by global sum.
// PDL: g_wsp (skt output — transitively complete) reduced in prologue.
// grid (A, B), block 192.
__global__ void k_av_fin() {
    const int a = blockIdx.x, b = blockIdx.y;
    const int tid = threadIdx.x;
    __shared__ float sInvS;
    if (tid < 32) {                              // prologue: weight sum
        float s = 0.f;
        #pragma unroll
        for (int j = 0; j < NSKT / 32; ++j) s += g_wsp[b][a][tid + j * 32];
        #pragma unroll
        for (int o = 16; o; o >>= 1) s += __shfl_down_sync(0xffffffffu, s, o);
        if (tid == 0) sInvS = 1.0f / s;
    }
    cudaGridDependencySynchronize();             // g_avpart ready
    cudaTriggerProgrammaticLaunchCompletion();
    float4 acc = make_float4(0.f, 0.f, 0.f, 0.f);
    #pragma unroll
    for (int s = 0; s < NSEG; ++s) {
        float4 p = g_avpart[b][s][a][tid];
        acc.x += p.x; acc.y += p.y; acc.z += p.z; acc.w += p.w;
    }
    __syncthreads();
    const float inv = sInvS;
    g_av[b][a][tid] = make_float4(acc.x * inv, acc.y * inv, acc.z * inv, acc.w * inv);
}

// ---------------------------------------------------------------
// Kernel 4: epilogue, packed f32x2 math, inline stage-2 softmax.
// PDL: b2 softmax (pure input) computed before syncing on g_av.
// x[b,t,d] = sum_a softmax_a(b2[t,:])[a] * agent_v[b,a,d]
// grid (T/32, B), block 192. Writes x once (100MB).
__global__ void k_epilogue(const float* __restrict__ b2,
                           ulonglong2* __restrict__ out) {
    const int tb = blockIdx.x, b = blockIdx.y;
    const int tid = threadIdx.x;
    const int t0 = tb * 32;
    __shared__ ull sp2[32][6];                   // (p,p) packed per [t][a]
    if (tid < 32) {                              // prologue
        int t = t0 + tid;
        float vv[A];
        float mx = -1e30f;
        #pragma unroll
        for (int a = 0; a < A; ++a) { vv[a] = b2[t * A + a]; mx = fmaxf(mx, vv[a]); }
        float sum = 0.f;
        #pragma unroll
        for (int a = 0; a < A; ++a) { vv[a] = expf(vv[a] - mx); sum += vv[a]; }
        float inv = 1.0f / sum;
        #pragma unroll
        for (int a = 0; a < A; ++a) sp2[tid][a] = pack2(vv[a] * inv);
    }
    cudaGridDependencySynchronize();             // g_av ready
    const ulonglong2* gav = (const ulonglong2*)&g_av[b][0][tid];
    ulonglong2 av0 = gav[0 * D4], av1 = gav[1 * D4], av2 = gav[2 * D4],
               av3 = gav[3 * D4], av4 = gav[4 * D4];
    __syncthreads();
    ulonglong2* ob = out + ((size_t)b * T + t0) * D4 + tid;
    #pragma unroll 8
    for (int tt = 0; tt < 32; ++tt) {
        ull p0 = sp2[tt][0], p1 = sp2[tt][1], p2 = sp2[tt][2],
            p3 = sp2[tt][3], p4 = sp2[tt][4];
        ull rL = mul2(p0, av0.x);
        ull rH = mul2(p0, av0.y);
        rL = fma2(p1, av1.x, rL); rH = fma2(p1, av1.y, rH);
        rL = fma2(p2, av2.x, rL); rH = fma2(p2, av2.y, rH);
        rL = fma2(p3, av3.x, rL); rH = fma2(p3, av3.y, rH);
        rL = fma2(p4, av4.x, rL); rH = fma2(p4, av4.y, rH);
        ob[(size_t)tt * D4] = make_ulonglong2(rL, rH);
    }
}

// ---------------------------------------------------------------
template <typename... Args>
static void launch_pdl(void (*kern)(Args...), dim3 grid, dim3 block,
                       bool pdl, Args... args) {
    cudaLaunchConfig_t cfg = {};
    cfg.gridDim = grid;
    cfg.blockDim = block;
    cfg.dynamicSmemBytes = 0;
    cfg.stream = 0;
    cudaLaunchAttribute attr[1];
    attr[0].id = cudaLaunchAttributeProgrammaticStreamSerialization;
    attr[0].val.programmaticStreamSerializationAllowed = 1;
    cfg.attrs = attr;
    cfg.numAttrs = pdl ? 1 : 0;
    cudaLaunchKernelEx(&cfg, kern, args...);
}

extern "C" void kernel_launch(void* const* d_in, const int* in_sizes, int n_in,
                              void* d_out, int out_size) {
    const float* qkv  = (const float*)d_in[0];        // [3,B,T,D]
    const int*   mask = (const int*)d_in[1];          // [B,T]
    const float* b1   = (const float*)d_in[2];        // [A,T]
    const float* b2   = (const float*)d_in[3];        // [T,A]

    const float4* q = (const float4*)qkv;
    const float4* k = (const float4*)(qkv + (size_t)B * T * D);
    const ulonglong2* v = (const ulonglong2*)(qkv + 2 * (size_t)B * T * D);

    launch_pdl(k_mean_part, dim3(NSEG1, B), dim3(192), false, q, mask);
    launch_pdl(k_mean_fin, dim3((B * D4 + 255) / 256), dim3(256), true);
    launch_pdl(k_skt, dim3(NSKT, B), dim3(256), true, k, b1);
    launch_pdl(k_av_part, dim3(NSEG, B), dim3(192), true, v);
    launch_pdl(k_av_fin, dim3(A, B), dim3(192), true);
    launch_pdl(k_epilogue, dim3(T / 32, B), dim3(192), true, b2,
               (ulonglong2*)d_out);
}